// round 6
// baseline (speedup 1.0000x reference)
#include <cuda_runtime.h>

#define N_    48
#define W_    16
#define X_    256
#define NW_   (N_ * W_)
#define SPLIT 6
#define GRID  (N_ * SPLIT)       // 288
#define CPB   (NW_ / SPLIT)      // 128 columns per block
#define INF_  1e30f
#define NWARP 16
#define BLK   (NWARP * 32)       // 512 threads
#define FULL  0xffffffffu

// Flat per-block partials (indexed by blockIdx)
__device__ float g_sumPos[GRID], g_sumNeg[GRID];
__device__ float g_maxV[GRID],   g_minV[GRID];
__device__ int   g_cntPos[GRID], g_cntNeg[GRID];
__device__ int   g_maxI[GRID],   g_minI[GRID];
__device__ int   g_accu[GRID];
__device__ float g_ltsum[GRID],  g_lhard[GRID];
__device__ int   g_count;        // zero-init; reset by finishing block

__global__ void __launch_bounds__(BLK, 2) triplet_kernel(
    const float* __restrict__ emb,   // [N, W, X] f32
    const float* __restrict__ lab,   // [N, W]    f32 (0/1)
    float* __restrict__ out)         // [337]     f32
{
    const int bid  = blockIdx.x;
    const int i    = bid / SPLIT;          // anchor index
    const int c    = bid % SPLIT;          // column chunk
    const int col0 = c * CPB;
    const int tid  = threadIdx.x;
    const int lane = tid & 31;
    const int warp = tid >> 5;

    __shared__ float s_own[W_];
    __shared__ float s_lab[W_];
    __shared__ float s_wsum[NWARP], s_whard[NWARP];
    __shared__ float s_wsp[NWARP], s_wsn[NWARP];
    __shared__ int   s_waccu[NWARP], s_wcp[NWARP], s_wcn[NWARP];
    __shared__ float s_wmaxv[NWARP], s_wminv[NWARP];
    __shared__ int   s_wmaxi[NWARP], s_wmini[NWARP];
    __shared__ int   s_last;

    // ---- anchor row straight into registers ----
    const float4* a4 = reinterpret_cast<const float4*>(emb + (size_t)i * W_ * X_);
    const float4 aA = a4[lane];
    const float4 aB = a4[lane + 32];

    if (tid < W_) s_lab[tid] = lab[i * W_ + tid];

    // ---- own-row distances: warp w computes own column w ----
    {
        const int jg = i * W_ + warp;
        const float4* f = reinterpret_cast<const float4*>(emb + (size_t)jg * X_);
        float4 va = f[lane], vb = f[lane + 32];
        float s = 0.f, d;
        d = aA.x - va.x; s = fmaf(d, d, s);
        d = aA.y - va.y; s = fmaf(d, d, s);
        d = aA.z - va.z; s = fmaf(d, d, s);
        d = aA.w - va.w; s = fmaf(d, d, s);
        d = aB.x - vb.x; s = fmaf(d, d, s);
        d = aB.y - vb.y; s = fmaf(d, d, s);
        d = aB.z - vb.z; s = fmaf(d, d, s);
        d = aB.w - vb.w; s = fmaf(d, d, s);
        #pragma unroll
        for (int off = 16; off; off >>= 1) s += __shfl_xor_sync(FULL, s, off);
        if (lane == 0) s_own[warp] = s;
    }
    __syncthreads();

    // ---- positive compaction: lane p gets distance of positive p ----
    float ownv = (lane < W_) ? s_own[lane] : 0.f;
    float labv = (lane < W_) ? s_lab[lane] : 0.f;
    const unsigned posmask = __ballot_sync(FULL, (lane < W_) && (labv > 0.f));
    const int npos = __popc(posmask);
    int srcl = __fns(posmask, 0, lane + 1);
    if (srcl < 0 || srcl > 31) srcl = 0;
    const float dp = __shfl_sync(FULL, ownv, srcl);    // valid for lane < npos
    const bool isPairLane = (lane < npos);

    // ---- fused distance + pair phase: each warp owns 8 chunk columns ----
    float tsum = 0.f; int thard = 0, taccu = 0;        // lane-parallel
    float sumPos = 0.f, sumNeg = 0.f;                  // identical in all lanes
    int   cntPos = 0, cntNeg = 0;
    float maxV = -INF_; int maxI = NW_;
    float minV =  INF_; int minI = NW_;

    #pragma unroll
    for (int it = 0; it < 2; it++) {
        float4 va[4], vb[4];
        int j[4];
        #pragma unroll
        for (int u = 0; u < 4; u++) {
            j[u] = col0 + warp + NWARP * (4 * it + u);
            const float4* f = reinterpret_cast<const float4*>(emb + (size_t)j[u] * X_);
            va[u] = f[lane]; vb[u] = f[lane + 32];
        }
        float s[4];
        #pragma unroll
        for (int u = 0; u < 4; u++) {
            float acc = 0.f, d;
            d = aA.x - va[u].x; acc = fmaf(d, d, acc);
            d = aA.y - va[u].y; acc = fmaf(d, d, acc);
            d = aA.z - va[u].z; acc = fmaf(d, d, acc);
            d = aA.w - va[u].w; acc = fmaf(d, d, acc);
            d = aB.x - vb[u].x; acc = fmaf(d, d, acc);
            d = aB.y - vb[u].y; acc = fmaf(d, d, acc);
            d = aB.z - vb[u].z; acc = fmaf(d, d, acc);
            d = aB.w - vb[u].w; acc = fmaf(d, d, acc);
            s[u] = acc;
        }
        #pragma unroll
        for (int off = 16; off; off >>= 1) {
            #pragma unroll
            for (int u = 0; u < 4; u++)
                s[u] += __shfl_xor_sync(FULL, s[u], off);
        }
        #pragma unroll
        for (int u = 0; u < 4; u++) {
            const float d = s[u];
            const int rel = j[u] - i * W_;
            const bool inRow  = ((unsigned)rel < (unsigned)W_);
            const bool isPos  = inRow && ((posmask >> (rel & 15)) & 1u);
            const bool isAnch = (rel == 0);
            if (isPos) {
                sumPos += d; cntPos++;
                if (d > maxV) { maxV = d; maxI = j[u]; }
            } else if (!isAnch) {
                sumNeg += d; cntNeg++;
                if (d < minV) { minV = d; minI = j[u]; }
                if (isPairLane) {
                    float v = dp - d + 1.0f;          // diff + MARGIN
                    tsum  += fmaxf(v, 0.f);
                    thard += (v > 1e-16f);
                    taccu += (dp < d);
                }
            }
        }
    }

    // ---- reduce lane-parallel quantities within warp ----
    #pragma unroll
    for (int off = 16; off; off >>= 1) {
        tsum  += __shfl_xor_sync(FULL, tsum,  off);
        thard += __shfl_xor_sync(FULL, thard, off);
        taccu += __shfl_xor_sync(FULL, taccu, off);
    }
    if (lane == 0) {
        s_wsum[warp] = tsum;  s_whard[warp] = (float)thard; s_waccu[warp] = taccu;
        s_wsp[warp] = sumPos; s_wsn[warp] = sumNeg;
        s_wcp[warp] = cntPos; s_wcn[warp] = cntNeg;
        s_wmaxv[warp] = maxV; s_wmaxi[warp] = maxI;
        s_wminv[warp] = minV; s_wmini[warp] = minI;
    }
    __syncthreads();

    // ---- block combine: warp 0, 16-lane butterfly; publish partials ----
    if (warp == 0) {
        const bool v = (lane < NWARP);
        float Tsum = v ? s_wsum[lane] : 0.f;
        float Hf   = v ? s_whard[lane] : 0.f;
        int   AC   = v ? s_waccu[lane] : 0;
        float SP   = v ? s_wsp[lane] : 0.f;
        float SN   = v ? s_wsn[lane] : 0.f;
        int   CP   = v ? s_wcp[lane] : 0;
        int   CN   = v ? s_wcn[lane] : 0;
        float MV   = v ? s_wmaxv[lane] : -INF_;
        int   MI   = v ? s_wmaxi[lane] : NW_;
        float mV   = v ? s_wminv[lane] :  INF_;
        int   mI   = v ? s_wmini[lane] : NW_;
        #pragma unroll
        for (int off = 16; off; off >>= 1) {
            Tsum += __shfl_xor_sync(FULL, Tsum, off);
            Hf   += __shfl_xor_sync(FULL, Hf,   off);
            AC   += __shfl_xor_sync(FULL, AC,   off);
            SP   += __shfl_xor_sync(FULL, SP,   off);
            SN   += __shfl_xor_sync(FULL, SN,   off);
            CP   += __shfl_xor_sync(FULL, CP,   off);
            CN   += __shfl_xor_sync(FULL, CN,   off);
            float xv = __shfl_xor_sync(FULL, MV, off);
            int   xi = __shfl_xor_sync(FULL, MI, off);
            if (xv > MV || (xv == MV && xi < MI)) { MV = xv; MI = xi; }
            float nv = __shfl_xor_sync(FULL, mV, off);
            int   ni = __shfl_xor_sync(FULL, mI, off);
            if (nv < mV || (nv == mV && ni < mI)) { mV = nv; mI = ni; }
        }
        if (lane == 0) {
            g_sumPos[bid] = SP;  g_sumNeg[bid] = SN;
            g_cntPos[bid] = CP;  g_cntNeg[bid] = CN;
            g_maxV[bid] = MV;    g_maxI[bid] = MI;
            g_minV[bid] = mV;    g_minI[bid] = mI;
            g_accu[bid] = AC;
            g_ltsum[bid] = Tsum; g_lhard[bid] = Hf;
            __threadfence();
            int g = atomicAdd(&g_count, 1);
            s_last = (g == GRID - 1);
        }
    }
    __syncthreads();

    // ================= FINISH: single last block does everything =================
    if (s_last) {
        __threadfence();   // acquire all blocks' partials

        // -- per-anchor outputs: thread a handles anchor a (a < 48) --
        if (tid < N_) {
            const int a = tid;
            float aSP = 0.f, aSN = 0.f;
            int   aAC = 0, aCP = 0, aCN = 0;
            float aMV = -INF_; int aMI = NW_;
            float amV =  INF_; int amI = NW_;
            #pragma unroll
            for (int cc = 0; cc < SPLIT; cc++) {
                const int b = a * SPLIT + cc;
                aSP += *(volatile float*)&g_sumPos[b];
                aSN += *(volatile float*)&g_sumNeg[b];
                aAC += *(volatile int*)&g_accu[b];
                aCP += *(volatile int*)&g_cntPos[b];
                aCN += *(volatile int*)&g_cntNeg[b];
                float xv = *(volatile float*)&g_maxV[b];
                int   xi = *(volatile int*)&g_maxI[b];
                if (xv > aMV || (xv == aMV && xi < aMI)) { aMV = xv; aMI = xi; }
                float nv = *(volatile float*)&g_minV[b];
                int   ni = *(volatile int*)&g_minI[b];
                if (nv < amV || (nv == amV && ni < amI)) { amV = nv; amI = ni; }
            }
            const float np = (float)aCP, nn = (float)aCN;
            const float npairs = np * nn;

            out[1 + 0 * N_ + a] = aMV;                   // max_anchor2pos
            out[1 + 1 * N_ + a] = amV;                   // min_anchor2neg
            out[1 + 2 * N_ + a] = amV - aMV;             // min_neg2pos
            out[1 + 3 * N_ + a] = (np * aSN - nn * aSP) / npairs;  // avg_neg2pos

            // ranks need this anchor's labels
            int ex = 0, pr = 0;
            #pragma unroll
            for (int w = 0; w < W_; w++) {
                const float lw = lab[a * W_ + w];
                const bool isP = (lw > 0.f);
                const int  col = a * W_ + w;
                if (((w == 0) || isP) && col <= amI) ex++;
                if (isP && col <= aMI) pr++;
            }
            out[1 + 4 * N_ + a] = (float)(amI - ex);     // neg_idx
            out[1 + 5 * N_ + a] = (float)(pr - 1);       // pos_idx
            out[1 + 6 * N_ + a] = (float)aAC / npairs;   // accu_ratio
        }

        // -- global loss: warp 2, lane-strided fixed mapping --
        if (warp == 2) {
            float s = 0.f, h = 0.f;
            for (int b = lane; b < GRID; b += 32) {
                s += *(volatile float*)&g_ltsum[b];
                h += *(volatile float*)&g_lhard[b];
            }
            #pragma unroll
            for (int off = 16; off; off >>= 1) {
                s += __shfl_xor_sync(FULL, s, off);
                h += __shfl_xor_sync(FULL, h, off);
            }
            if (lane == 0) {
                out[0] = s / (h + 1e-16f);
                g_count = 0;   // reset for next graph replay
            }
        }
    }
}

extern "C" void kernel_launch(void* const* d_in, const int* in_sizes, int n_in,
                              void* d_out, int out_size) {
    const float* emb = (const float*)d_in[0];   // pred_embeddings [48,16,256]
    const float* lab = (const float*)d_in[1];   // pos_neg_label  [48,16]
    float* out = (float*)d_out;                 // 337 floats

    triplet_kernel<<<GRID, BLK>>>(emb, lab, out);
}

// round 7
// speedup vs baseline: 1.0376x; 1.0376x over previous
#include <cuda_runtime.h>

#define N_    48
#define W_    16
#define X_    256
#define NW_   (N_ * W_)
#define SPLIT 3
#define GRID  (N_ * SPLIT)       // 144
#define CPB   (NW_ / SPLIT)      // 256 columns per block
#define INF_  1e30f
#define NWARP 32
#define BLK   1024
#define FULL  0xffffffffu
#define CPW   (CPB / NWARP)      // 8 columns per warp

// Flat per-block partials
__device__ float    g_ltsum[GRID];
__device__ unsigned g_combo[GRID];     // hard | (accu<<16)
__device__ float    g_sumNeg[GRID];
__device__ float    g_minV[GRID];
__device__ int      g_minI[GRID];
// Per-anchor pos stats (single writer: the own-chunk block)
__device__ float    g_sumPos[N_];
__device__ float    g_maxV[N_];
__device__ int      g_maxI[N_];
__device__ int      g_count;           // zero-init; reset by finishing warp

__global__ void __launch_bounds__(BLK, 1) triplet_kernel(
    const float* __restrict__ emb,   // [N, W, X] f32
    const float* __restrict__ lab,   // [N, W]    f32 (0/1)
    float* __restrict__ out)         // [337]     f32
{
    const int bid  = blockIdx.x;
    const int i    = bid / SPLIT;          // anchor index
    const int c    = bid % SPLIT;          // column chunk
    const int col0 = c * CPB;
    const int tid  = threadIdx.x;
    const int lane = tid & 31;
    const int warp = tid >> 5;
    const bool hasOwn = (c == (i >> 4));   // own row lives in chunk i/16

    __shared__ float    s_own[W_];
    __shared__ float    s_tsum[NWARP];
    __shared__ unsigned s_combo[NWARP];
    __shared__ float    s_sn[NWARP], s_minv[NWARP];
    __shared__ int      s_mini[NWARP];
    __shared__ float    s_sp[NWARP], s_maxv[NWARP];
    __shared__ int      s_maxi[NWARP];

    // labels straight to registers (per-warp redundant, L1-hit)
    const float labv = (lane < W_) ? lab[i * W_ + lane] : 0.f;

    // anchor row in registers
    const float4* a4 = reinterpret_cast<const float4*>(emb + (size_t)i * W_ * X_);
    const float4 aA = a4[lane];
    const float4 aB = a4[lane + 32];

    // ---- own-row distance: warp w (<16) computes own column w ----
    if (warp < W_) {
        const float4* f = reinterpret_cast<const float4*>(emb + (size_t)(i * W_ + warp) * X_);
        float4 va = f[lane], vb = f[lane + 32];
        float s = 0.f, d;
        d = aA.x - va.x; s = fmaf(d, d, s);
        d = aA.y - va.y; s = fmaf(d, d, s);
        d = aA.z - va.z; s = fmaf(d, d, s);
        d = aA.w - va.w; s = fmaf(d, d, s);
        d = aB.x - vb.x; s = fmaf(d, d, s);
        d = aB.y - vb.y; s = fmaf(d, d, s);
        d = aB.z - vb.z; s = fmaf(d, d, s);
        d = aB.w - vb.w; s = fmaf(d, d, s);
        #pragma unroll
        for (int off = 16; off; off >>= 1) s += __shfl_xor_sync(FULL, s, off);
        if (lane == 0) s_own[warp] = s;
    }

    // ---- 8 column distances, 2 batches of 4 (loads overlap own-row phase) ----
    float dcol[CPW];
    #pragma unroll
    for (int bt = 0; bt < 2; bt++) {
        float4 va[4], vb[4];
        #pragma unroll
        for (int u = 0; u < 4; u++) {
            const int j = col0 + warp + NWARP * (4 * bt + u);
            const float4* f = reinterpret_cast<const float4*>(emb + (size_t)j * X_);
            va[u] = f[lane]; vb[u] = f[lane + 32];
        }
        float s[4];
        #pragma unroll
        for (int u = 0; u < 4; u++) {
            float acc = 0.f, d;
            d = aA.x - va[u].x; acc = fmaf(d, d, acc);
            d = aA.y - va[u].y; acc = fmaf(d, d, acc);
            d = aA.z - va[u].z; acc = fmaf(d, d, acc);
            d = aA.w - va[u].w; acc = fmaf(d, d, acc);
            d = aB.x - vb[u].x; acc = fmaf(d, d, acc);
            d = aB.y - vb[u].y; acc = fmaf(d, d, acc);
            d = aB.z - vb[u].z; acc = fmaf(d, d, acc);
            d = aB.w - vb[u].w; acc = fmaf(d, d, acc);
            s[u] = acc;
        }
        #pragma unroll
        for (int off = 16; off; off >>= 1) {
            #pragma unroll
            for (int u = 0; u < 4; u++)
                s[u] += __shfl_xor_sync(FULL, s[u], off);
        }
        #pragma unroll
        for (int u = 0; u < 4; u++) dcol[4 * bt + u] = s[u];
    }
    __syncthreads();

    // ---- positive compaction ----
    const float ownv = (lane < W_) ? s_own[lane] : 0.f;
    const unsigned posmask = __ballot_sync(FULL, (lane < W_) && (labv > 0.f));
    const int npos = __popc(posmask);
    int srcl = __fns(posmask, 0, lane + 1);
    if (srcl < 0 || srcl > 31) srcl = 0;
    const float dp = __shfl_sync(FULL, ownv, srcl);
    const bool isPairLane = (lane < npos);

    // ---- pair phase over the 8 register-resident distances ----
    float tsum = 0.f; int hard = 0, accu = 0;        // lane-parallel
    float sumNeg = 0.f;                              // uniform across lanes
    float minV = INF_; int minI = NW_;
    float sumPos = 0.f, maxV = -INF_; int maxI = NW_;

    if (hasOwn) {
        #pragma unroll
        for (int k = 0; k < CPW; k++) {
            const int j = col0 + warp + NWARP * k;
            const float d = dcol[k];
            const int rel = j - i * W_;
            const bool inRow  = ((unsigned)rel < (unsigned)W_);
            const bool isPos  = inRow && ((posmask >> (rel & 31)) & 1u);
            const bool isAnch = (rel == 0);
            if (isPos) {
                sumPos += d;
                if (d > maxV) { maxV = d; maxI = j; }
            } else if (!isAnch) {
                sumNeg += d;
                if (d < minV) { minV = d; minI = j; }
                if (isPairLane) {
                    float v = dp - d + 1.0f;
                    tsum += fmaxf(v, 0.f);
                    hard += (v > 1e-16f);
                    accu += (dp < d);
                }
            }
        }
    } else {
        // all 8 columns are negatives — branch-free
        #pragma unroll
        for (int k = 0; k < CPW; k++) {
            const int j = col0 + warp + NWARP * k;
            const float d = dcol[k];
            sumNeg += d;
            if (d < minV) { minV = d; minI = j; }
            if (isPairLane) {
                float v = dp - d + 1.0f;
                tsum += fmaxf(v, 0.f);
                hard += (v > 1e-16f);
                accu += (dp < d);
            }
        }
    }

    // ---- warp reduce (only lane-parallel quantities; rest uniform) ----
    unsigned combo = (unsigned)hard | ((unsigned)accu << 16);
    #pragma unroll
    for (int off = 16; off; off >>= 1) {
        tsum  += __shfl_xor_sync(FULL, tsum,  off);
        combo += __shfl_xor_sync(FULL, combo, off);
    }
    if (lane == 0) {
        s_tsum[warp] = tsum;  s_combo[warp] = combo;
        s_sn[warp] = sumNeg;  s_minv[warp] = minV;  s_mini[warp] = minI;
        if (hasOwn) { s_sp[warp] = sumPos; s_maxv[warp] = maxV; s_maxi[warp] = maxI; }
    }
    __syncthreads();

    // ---- block combine + publish + finish, all in warp 0 ----
    if (warp == 0) {
        float    T  = s_tsum[lane];
        unsigned C  = s_combo[lane];
        float    SN = s_sn[lane];
        float    mV = s_minv[lane];
        int      mI = s_mini[lane];
        float    SP = hasOwn ? s_sp[lane]   : 0.f;
        float    MV = hasOwn ? s_maxv[lane] : -INF_;
        int      MI = hasOwn ? s_maxi[lane] : NW_;
        #pragma unroll
        for (int off = 16; off; off >>= 1) {
            T  += __shfl_xor_sync(FULL, T,  off);
            C  += __shfl_xor_sync(FULL, C,  off);
            SN += __shfl_xor_sync(FULL, SN, off);
            float nv = __shfl_xor_sync(FULL, mV, off);
            int   ni = __shfl_xor_sync(FULL, mI, off);
            if (nv < mV || (nv == mV && ni < mI)) { mV = nv; mI = ni; }
            float xv = __shfl_xor_sync(FULL, MV, off);
            int   xi = __shfl_xor_sync(FULL, MI, off);
            if (xv > MV || (xv == MV && xi < MI)) { MV = xv; MI = xi; }
            SP += __shfl_xor_sync(FULL, SP, off);
        }
        int last = 0;
        if (lane == 0) {
            g_ltsum[bid] = T;  g_combo[bid] = C;
            g_sumNeg[bid] = SN; g_minV[bid] = mV; g_minI[bid] = mI;
            if (hasOwn) { g_sumPos[i] = SP; g_maxV[i] = MV; g_maxI[i] = MI; }
            __threadfence();
            last = (atomicAdd(&g_count, 1) == GRID - 1);
        }
        last = __shfl_sync(FULL, last, 0);

        if (last) {
            __threadfence();   // acquire all blocks' partials

            // -- global loss: lane-strided fixed mapping --
            float s = 0.f, h = 0.f;
            for (int b = lane; b < GRID; b += 32) {
                s += ((volatile float*)g_ltsum)[b];
                h += (float)(((volatile unsigned*)g_combo)[b] & 0xffffu);
            }
            #pragma unroll
            for (int off = 16; off; off >>= 1) {
                s += __shfl_xor_sync(FULL, s, off);
                h += __shfl_xor_sync(FULL, h, off);
            }
            if (lane == 0) {
                out[0] = s / (h + 1e-16f);
                g_count = 0;   // reset for next graph replay
            }

            // -- per-anchor outputs: lane handles anchors lane, lane+32 --
            for (int a = lane; a < N_; a += 32) {
                float sn = 0.f; int acc = 0;
                float mv = INF_; int mi = NW_;
                #pragma unroll
                for (int cc = 0; cc < SPLIT; cc++) {
                    const int b = a * SPLIT + cc;
                    sn  += ((volatile float*)g_sumNeg)[b];
                    acc += (int)(((volatile unsigned*)g_combo)[b] >> 16);
                    float nv = ((volatile float*)g_minV)[b];
                    int   ni = ((volatile int*)g_minI)[b];
                    if (nv < mv || (nv == mv && ni < mi)) { mv = nv; mi = ni; }
                }
                const float sp  = ((volatile float*)g_sumPos)[a];
                const float MV2 = ((volatile float*)g_maxV)[a];
                const int   MI2 = ((volatile int*)g_maxI)[a];

                int np = 0, ex = 0, pr = 0;
                #pragma unroll
                for (int w = 0; w < W_; w++) {
                    const float lw = lab[a * W_ + w];
                    const bool isP = (lw > 0.f);
                    const int  col = a * W_ + w;
                    np += isP;
                    if (((w == 0) || isP) && col <= mi) ex++;
                    if (isP && col <= MI2) pr++;
                }
                const int npext = np + ((lab[a * W_] > 0.f) ? 0 : 1);
                const float nn = (float)(NW_ - npext);
                const float npf = (float)np;
                const float npairs = npf * nn;

                out[1 + 0 * N_ + a] = MV2;                       // max_anchor2pos
                out[1 + 1 * N_ + a] = mv;                        // min_anchor2neg
                out[1 + 2 * N_ + a] = mv - MV2;                  // min_neg2pos
                out[1 + 3 * N_ + a] = (npf * sn - nn * sp) / npairs;  // avg_neg2pos
                out[1 + 4 * N_ + a] = (float)(mi - ex);          // neg_idx
                out[1 + 5 * N_ + a] = (float)(pr - 1);           // pos_idx
                out[1 + 6 * N_ + a] = (float)acc / npairs;       // accu_ratio
            }
        }
    }
}

extern "C" void kernel_launch(void* const* d_in, const int* in_sizes, int n_in,
                              void* d_out, int out_size) {
    const float* emb = (const float*)d_in[0];   // pred_embeddings [48,16,256]
    const float* lab = (const float*)d_in[1];   // pos_neg_label  [48,16]
    float* out = (float*)d_out;                 // 337 floats

    triplet_kernel<<<GRID, BLK>>>(emb, lab, out);
}